// round 1
// baseline (speedup 1.0000x reference)
#include <cuda_runtime.h>
#include <cstdint>

// LaneATT line NMS, exact reimplementation of the JAX reference:
//   order = stable argsort(-scores)
//   greedy keep: candidate i kept iff no previously-kept j suppresses it,
//     S[j][i] = (pe>=ps) && (sum_{k in [ps,pe]} |x_j[k]-x_i[k]| / max(pe-ps+1,1) < thr)
//   output: topk kept rows (proposal 77 cols + score), zero-padded, then num_kept.
//
// Key insight: suppression only ever comes from KEPT items (<= topk = 8), so the
// O(n^2 * 72) matrix in the reference collapses to an O(n * topk * 72) walk that
// in practice terminates after ~topk+epsilon candidates. The dominant cost is the
// stable descending sort of 8192 scores, done as an in-shared-memory bitonic sort
// on packed u64 keys (desc score, asc index tiebreak == stable argsort(-s)).

#define N_OFFSETS 72
#define N_STRIPS 71
#define PROP_COLS 77
#define MAX_KEPT 32
#define NT 1024

__global__ __launch_bounds__(NT, 1)
void laneatt_nms_kernel(const float* __restrict__ proposals,
                        const float* __restrict__ scores,
                        const int* __restrict__ thres_ptr,
                        const int* __restrict__ topk_ptr,
                        float* __restrict__ out,
                        int out_size, int n, int npow2)
{
    extern __shared__ uint64_t keys[];   // npow2 entries

    __shared__ float kept_xs[MAX_KEPT][N_OFFSETS];
    __shared__ int   kept_s[MAX_KEPT];
    __shared__ int   kept_e[MAX_KEPT];
    __shared__ int   kept_gi[MAX_KEPT];
    __shared__ float cand_xs[N_OFFSETS];
    __shared__ int   sh_cs, sh_ce;
    __shared__ int   supp[MAX_KEPT];
    __shared__ int   sh_accept;

    const int tid = threadIdx.x;

    // ---- decode scalar params (robust to int32 or float32 encoding) ----
    int tv = *thres_ptr;
    float thr = (tv >= 0 && tv < 1000000) ? (float)tv : __int_as_float(tv);
    int tk = *topk_ptr;
    if (tk <= 0 || tk > 100000) tk = (int)__int_as_float(tk);
    if (tk > MAX_KEPT) tk = MAX_KEPT;

    // ---- build sort keys: descending score, ascending index (stable) ----
    for (int i = tid; i < npow2; i += NT) {
        if (i < n) {
            uint32_t b = __float_as_uint(scores[i]);
            // map float bits -> monotonically increasing uint
            b = (b & 0x80000000u) ? ~b : (b | 0x80000000u);
            uint32_t dk = 0xFFFFFFFFu - b;              // descending score
            keys[i] = ((uint64_t)dk << 32) | (uint32_t)i;
        } else {
            keys[i] = 0xFFFFFFFFFFFFFFFFull;            // pad to end
        }
    }
    __syncthreads();

    // ---- bitonic sort (ascending) ----
    for (int k = 2; k <= npow2; k <<= 1) {
        for (int j = k >> 1; j > 0; j >>= 1) {
            for (int i = tid; i < npow2; i += NT) {
                int ixj = i ^ j;
                if (ixj > i) {
                    uint64_t a = keys[i];
                    uint64_t b = keys[ixj];
                    bool up = ((i & k) == 0);
                    if ((a > b) == up) { keys[i] = b; keys[ixj] = a; }
                }
            }
            __syncthreads();
        }
    }

    // ---- greedy walk: test each candidate against current kept set ----
    const int warp = tid >> 5;
    const int lane = tid & 31;
    int kc = 0;

    for (int i = 0; i < n && kc < tk; ++i) {
        int gi = (int)(keys[i] & 0xFFFFFFFFull);
        const float* row = proposals + (size_t)gi * PROP_COLS;

        if (tid < N_OFFSETS) cand_xs[tid] = row[5 + tid];
        if (tid == 0) {
            int s = (int)rintf(row[2] * (float)N_STRIPS);   // round-half-even
            int e = min(s + (int)rintf(row[4]) - 1, N_STRIPS);
            sh_cs = s; sh_ce = e;
        }
        __syncthreads();

        // warp w tests kept item w against the candidate
        if (warp < kc) {
            int ps = max(sh_cs, kept_s[warp]);
            int pe = min(sh_ce, kept_e[warp]);
            float d = 0.0f;
            #pragma unroll
            for (int k = 0; k < 3; ++k) {
                int off = lane + k * 32;
                if (off < N_OFFSETS && off >= ps && off <= pe)
                    d += fabsf(cand_xs[off] - kept_xs[warp][off]);
            }
            #pragma unroll
            for (int o = 16; o > 0; o >>= 1)
                d += __shfl_xor_sync(0xFFFFFFFFu, d, o);
            if (lane == 0) {
                float cnt = (float)max(pe - ps + 1, 1);
                supp[warp] = (pe >= ps) && (d / cnt < thr);
            }
        }
        __syncthreads();

        if (tid == 0) {
            int s = 0;
            for (int j = 0; j < kc; ++j) s |= supp[j];
            sh_accept = !s;
        }
        __syncthreads();

        if (sh_accept) {   // uniform across block
            if (tid < N_OFFSETS) kept_xs[kc][tid] = cand_xs[tid];
            if (tid == 0) { kept_s[kc] = sh_cs; kept_e[kc] = sh_ce; kept_gi[kc] = gi; }
            __syncthreads();
            ++kc;
        }
    }
    // num_kept = min(total_keep, topk). If we stopped at kc==tk, min saturates to tk;
    // if the list was exhausted, kc is the exact total keep count. Either way: kc.

    // ---- write output: tk rows of 78 (proposal cols + score), then num_kept ----
    int row_elems = tk * (PROP_COLS + 1);
    for (int idx = tid; idx < out_size; idx += NT) {
        float v = 0.0f;
        if (idx < row_elems) {
            int r = idx / (PROP_COLS + 1);
            int c = idx - r * (PROP_COLS + 1);
            if (r < kc) {
                int gi = kept_gi[r];
                v = (c < PROP_COLS) ? proposals[(size_t)gi * PROP_COLS + c]
                                    : scores[gi];
            }
        } else if (idx == row_elems) {
            v = (float)kc;
        }
        out[idx] = v;
    }
}

extern "C" void kernel_launch(void* const* d_in, const int* in_sizes, int n_in,
                              void* d_out, int out_size) {
    const float* proposals = (const float*)d_in[0];
    const float* scores    = (const float*)d_in[1];
    const int*   thres     = (const int*)d_in[2];
    const int*   topk      = (const int*)d_in[3];
    float* out = (float*)d_out;

    int n = in_sizes[1];               // number of proposals (scores count)
    int npow2 = 1;
    while (npow2 < n) npow2 <<= 1;

    size_t smem = (size_t)npow2 * sizeof(uint64_t);
    static bool attr_set = false;      // idempotent attribute, not a work guard
    if (!attr_set) {
        cudaFuncSetAttribute(laneatt_nms_kernel,
                             cudaFuncAttributeMaxDynamicSharedMemorySize,
                             (int)smem);
        attr_set = true;
    }

    laneatt_nms_kernel<<<1, NT, smem>>>(proposals, scores, thres, topk,
                                        out, out_size, n, npow2);
}

// round 2
// speedup vs baseline: 4.9084x; 4.9084x over previous
#include <cuda_runtime.h>
#include <cstdint>

// LaneATT line NMS — Round 2.
//
// Reference semantics: stable argsort(-scores); greedy keep where suppression
// only comes from already-KEPT items; output topk rows (77 cols + score),
// zero-padded, then num_kept = min(total_keep, topk).
//
// R1 lesson: the full bitonic sort (91 passes) was ~95% of 103us. The greedy
// walk only consumes candidates in descending order until topk are kept, so we
// replace the sort with ITERATIVE BLOCK ARGMAX over packed u64 keys in shared:
//   key = (orderable_score << 32) | (0xFFFFFFFF - idx)
// max(key) == highest score, tie -> lowest index (stable-sort equivalence).
// Sentinel 0 marks removed slots (valid keys always have a nonzero low word).
// Loop until topk kept OR pool exhausted — exact num_kept in the under-full
// case, correct for arbitrary inputs (only adversarially slow, not wrong).

#define N_OFFSETS 72
#define N_STRIPS 71
#define PROP_COLS 77
#define MAX_KEPT 32
#define NT 1024
#define NWARPS (NT / 32)

__global__ __launch_bounds__(NT, 1)
void laneatt_nms_kernel(const float* __restrict__ proposals,
                        const float* __restrict__ scores,
                        const int* __restrict__ thres_ptr,
                        const int* __restrict__ topk_ptr,
                        float* __restrict__ out,
                        int out_size, int n)
{
    extern __shared__ uint64_t keys[];          // n entries

    __shared__ uint64_t wmax[NWARPS];
    __shared__ uint64_t sh_win;
    __shared__ float kept_xs[MAX_KEPT][N_OFFSETS];
    __shared__ int   kept_s[MAX_KEPT];
    __shared__ int   kept_e[MAX_KEPT];
    __shared__ int   kept_gi[MAX_KEPT];
    __shared__ float cand_xs[N_OFFSETS];
    __shared__ int   sh_cs, sh_ce;
    __shared__ int   supp[MAX_KEPT];
    __shared__ int   sh_accept;

    const int tid  = threadIdx.x;
    const int warp = tid >> 5;
    const int lane = tid & 31;

    // ---- decode scalar params (robust to int32 or float32 bit encoding) ----
    int tv = *thres_ptr;
    float thr = (tv >= 0 && tv < 1000000) ? (float)tv : __int_as_float(tv);
    int tk = *topk_ptr;
    if (tk <= 0 || tk > 100000) tk = (int)__int_as_float(tk);
    if (tk > MAX_KEPT) tk = MAX_KEPT;

    // ---- build selection keys ----
    for (int i = tid; i < n; i += NT) {
        uint32_t b = __float_as_uint(scores[i]);
        b = (b & 0x80000000u) ? ~b : (b | 0x80000000u);   // orderable float bits
        keys[i] = ((uint64_t)b << 32) | (0xFFFFFFFFu - (uint32_t)i);
    }
    __syncthreads();

    int kc = 0;

    for (int it = 0; it < n && kc < tk; ++it) {
        // ---- block argmax over keys ----
        uint64_t m = 0;
        for (int i = tid; i < n; i += NT) {
            uint64_t v = keys[i];
            if (v > m) m = v;
        }
        #pragma unroll
        for (int o = 16; o > 0; o >>= 1) {
            uint64_t v = __shfl_xor_sync(0xFFFFFFFFu, m, o);
            if (v > m) m = v;
        }
        if (lane == 0) wmax[warp] = m;
        __syncthreads();
        if (warp == 0) {
            uint64_t v = (lane < NWARPS) ? wmax[lane] : 0;
            #pragma unroll
            for (int o = 16; o > 0; o >>= 1) {
                uint64_t u = __shfl_xor_sync(0xFFFFFFFFu, v, o);
                if (u > v) v = u;
            }
            if (lane == 0) sh_win = v;
        }
        __syncthreads();

        uint64_t win = sh_win;
        if (win == 0) break;                       // pool exhausted
        int gi = (int)(0xFFFFFFFFu - (uint32_t)(win & 0xFFFFFFFFull));

        // ---- load candidate row; clear winner slot ----
        const float* row = proposals + (size_t)gi * PROP_COLS;
        if (tid < N_OFFSETS) cand_xs[tid] = row[5 + tid];
        if (tid == 0) {
            keys[gi] = 0;                          // remove from pool
            int s = (int)rintf(row[2] * (float)N_STRIPS);  // round half-even
            int e = min(s + (int)rintf(row[4]) - 1, N_STRIPS);
            sh_cs = s; sh_ce = e;
        }
        __syncthreads();

        // ---- warp w tests kept item w against the candidate ----
        if (warp < kc) {
            int ps = max(sh_cs, kept_s[warp]);
            int pe = min(sh_ce, kept_e[warp]);
            float d = 0.0f;
            #pragma unroll
            for (int k = 0; k < 3; ++k) {
                int off = lane + k * 32;
                if (off < N_OFFSETS && off >= ps && off <= pe)
                    d += fabsf(cand_xs[off] - kept_xs[warp][off]);
            }
            #pragma unroll
            for (int o = 16; o > 0; o >>= 1)
                d += __shfl_xor_sync(0xFFFFFFFFu, d, o);
            if (lane == 0) {
                float cnt = (float)max(pe - ps + 1, 1);
                supp[warp] = (pe >= ps) && (d / cnt < thr);
            }
        }
        __syncthreads();

        if (tid == 0) {
            int s = 0;
            for (int j = 0; j < kc; ++j) s |= supp[j];
            sh_accept = !s;
        }
        __syncthreads();

        if (sh_accept) {                           // uniform across block
            if (tid < N_OFFSETS) kept_xs[kc][tid] = cand_xs[tid];
            if (tid == 0) { kept_s[kc] = sh_cs; kept_e[kc] = sh_ce; kept_gi[kc] = gi; }
            ++kc;                                  // visible next iter after syncs
        }
    }
    // kc == num_kept in all cases (saturates at tk, exact when list exhausted).

    // ---- write output: tk rows of 78 (proposal + score), then num_kept ----
    __syncthreads();
    int row_elems = tk * (PROP_COLS + 1);
    for (int idx = tid; idx < out_size; idx += NT) {
        float v = 0.0f;
        if (idx < row_elems) {
            int r = idx / (PROP_COLS + 1);
            int c = idx - r * (PROP_COLS + 1);
            if (r < kc) {
                int gi = kept_gi[r];
                v = (c < PROP_COLS) ? proposals[(size_t)gi * PROP_COLS + c]
                                    : scores[gi];
            }
        } else if (idx == row_elems) {
            v = (float)kc;
        }
        out[idx] = v;
    }
}

extern "C" void kernel_launch(void* const* d_in, const int* in_sizes, int n_in,
                              void* d_out, int out_size) {
    const float* proposals = (const float*)d_in[0];
    const float* scores    = (const float*)d_in[1];
    const int*   thres     = (const int*)d_in[2];
    const int*   topk      = (const int*)d_in[3];
    float* out = (float*)d_out;

    int n = in_sizes[1];                          // scores element count
    size_t smem = (size_t)n * sizeof(uint64_t);

    static bool attr_set = false;                 // idempotent attribute only
    if (!attr_set) {
        cudaFuncSetAttribute(laneatt_nms_kernel,
                             cudaFuncAttributeMaxDynamicSharedMemorySize,
                             (int)smem);
        attr_set = true;
    }

    laneatt_nms_kernel<<<1, NT, smem>>>(proposals, scores, thres, topk,
                                        out, out_size, n);
}